// round 11
// baseline (speedup 1.0000x reference)
#include <cuda_runtime.h>
#include <cuda_bf16.h>
#include <cuda_fp16.h>
#include <cstdint>

#define BB 2
#define SS 2048
#define DD 1024
#define HH 16
#define MM (BB*SS)             // 4096

// GEMM tiling: 128x128 tile, K-chunk 64 (128B rows, SW128 swizzle)
#define TM 128
#define TN 128
#define KC 64
#define NCH (DD/KC)            // 16
#define NSTAGE 3               // MUST be >=3: issue(kc+2) while reading kc
#define ARR_BYTES 16384        // 128 rows x 128B
#define STAGE_BYTES 65536
#define OFF_AH 0
#define OFF_AU 16384
#define OFF_BH 32768
#define OFF_BU 49152
#define GEMM_SMEM (NSTAGE*STAGE_BYTES)   // 196608

// Karatsuba combine: C = (1 - 2^-6) * acc_hh + acc_uu
#define C_MAIN 0.984375f

// Attention v2 tiling
#define QSTRIDE 68
#define KSTRIDE 68
#define SST 132
#define ATT2_SMEM ((64*QSTRIDE + 128*KSTRIDE + 128*KSTRIDE)*4)   // 87040 B

// ---------------------------------------------------------------------------
// Scratch (device globals: allocation-free rule)
// ---------------------------------------------------------------------------
__device__ float g_Q[(size_t)MM * DD];
__device__ float g_K[(size_t)MM * DD];
__device__ float g_V[(size_t)MM * DD];
__device__ __half g_Ah[(size_t)MM * DD];
__device__ __half g_Au[(size_t)MM * DD];
__device__ __half g_Wh[(size_t)4 * DD * DD];   // wq,wk,wv,wo
__device__ __half g_Wu[(size_t)4 * DD * DD];
__device__ __half g_Ch[(size_t)MM * DD];
__device__ __half g_Cu[(size_t)MM * DD];

// ---------------------------------------------------------------------------
// Helpers
// ---------------------------------------------------------------------------
__device__ __forceinline__ uint32_t smem_u32(const void* p) {
    uint32_t a;
    asm("{ .reg .u64 t; cvta.to.shared.u64 t, %1; cvt.u32.u64 %0, t; }"
        : "=r"(a) : "l"(p));
    return a;
}

__device__ __forceinline__ void cpasync16(uint32_t dst, const void* src) {
    asm volatile("cp.async.cg.shared.global [%0], [%1], 16;"
                 :: "r"(dst), "l"(src));
}
#define CP_COMMIT() asm volatile("cp.async.commit_group;" ::: "memory")
#define CP_WAIT1()  asm volatile("cp.async.wait_group 1;" ::: "memory")
#define CP_WAIT0()  asm volatile("cp.async.wait_group 0;" ::: "memory")

__device__ __forceinline__ void ldm4(uint32_t* r, uint32_t addr) {
    asm volatile("ldmatrix.sync.aligned.m8n8.x4.shared.b16 {%0,%1,%2,%3}, [%4];"
                 : "=r"(r[0]), "=r"(r[1]), "=r"(r[2]), "=r"(r[3]) : "r"(addr));
}

__device__ __forceinline__ void mma_f32(float* c, const uint32_t* a,
                                        uint32_t b0, uint32_t b1) {
    asm volatile(
        "mma.sync.aligned.m16n8k16.row.col.f32.f16.f16.f32 "
        "{%0,%1,%2,%3}, {%4,%5,%6,%7}, {%8,%9}, {%0,%1,%2,%3};"
        : "+f"(c[0]), "+f"(c[1]), "+f"(c[2]), "+f"(c[3])
        : "r"(a[0]), "r"(a[1]), "r"(a[2]), "r"(a[3]), "r"(b0), "r"(b1));
}

// x -> H = fp16(x), U = fp16(2^-3*H + 2^3*(x-H))
__device__ __forceinline__ void ksplit(float x, __half& h, __half& u) {
    h = __float2half_rn(x);
    const float hf = __half2float(h);
    u = __float2half_rn(fmaf(0.125f, hf, 8.0f * (x - hf)));
}

// ---------------------------------------------------------------------------
// Zero-fill (replaces cudaMemsetAsync: big grid, co-schedules with GEMMs)
// ---------------------------------------------------------------------------
__global__ void __launch_bounds__(256) zero_kernel(float4* __restrict__ p, size_t n4)
{
    const size_t stride = (size_t)gridDim.x * 256;
    const float4 z = make_float4(0.f, 0.f, 0.f, 0.f);
    for (size_t i = (size_t)blockIdx.x * 256 + threadIdx.x; i < n4; i += stride)
        p[i] = z;
}

// ---------------------------------------------------------------------------
// Split pass: q + 4 weights -> fp16 H / U
// ---------------------------------------------------------------------------
__global__ void __launch_bounds__(256) split_kernel(const float* __restrict__ q,
                                                    const float* __restrict__ wq,
                                                    const float* __restrict__ wk,
                                                    const float* __restrict__ wv,
                                                    const float* __restrict__ wo)
{
    const size_t i4 = (size_t)blockIdx.x * 256 + threadIdx.x;
    const float* src;
    __half *dh, *du;
    size_t e;
    if (i4 < 1048576) {
        src = q; e = i4;
        dh = g_Ah; du = g_Au;
    } else {
        const size_t r = i4 - 1048576;
        const int w = (int)(r >> 18);
        e = r & 262143;
        src = (w == 0) ? wq : (w == 1) ? wk : (w == 2) ? wv : wo;
        dh = g_Wh + (size_t)w * DD * DD;
        du = g_Wu + (size_t)w * DD * DD;
    }
    const float4 v = ((const float4*)src)[e];
    __half h[4], u[4];
    ksplit(v.x, h[0], u[0]); ksplit(v.y, h[1], u[1]);
    ksplit(v.z, h[2], u[2]); ksplit(v.w, h[3], u[3]);
    *(ushort4*)(dh + e * 4) = make_ushort4(*(unsigned short*)&h[0], *(unsigned short*)&h[1],
                                           *(unsigned short*)&h[2], *(unsigned short*)&h[3]);
    *(ushort4*)(du + e * 4) = make_ushort4(*(unsigned short*)&u[0], *(unsigned short*)&u[1],
                                           *(unsigned short*)&u[2], *(unsigned short*)&u[3]);
}

// ---------------------------------------------------------------------------
// fp16 Karatsuba GEMM (unchanged from round 9/10)
// ---------------------------------------------------------------------------
__device__ __forceinline__ void gemm_body(const __half* __restrict__ Ah,
                                          const __half* __restrict__ Au,
                                          const __half* __restrict__ Wh,
                                          const __half* __restrict__ Wu,
                                          float* __restrict__ C,
                                          const float* __restrict__ bias)
{
    extern __shared__ char dsm[];
    const uint32_t sb = smem_u32(dsm);
    const int tid  = threadIdx.x;
    const int wid  = tid >> 5;
    const int lane = tid & 31;
    const int wm   = wid >> 2;
    const int wn   = wid & 3;
    const int brow = blockIdx.y * TM;
    const int bcol = blockIdx.x * TN;

    const __half* Abase[2] = { Ah + (size_t)brow * DD, Au + (size_t)brow * DD };
    const __half* Bbase[2] = { Wh + (size_t)bcol * DD, Wu + (size_t)bcol * DD };

    float acc[4][4][4];
    float acc2[4][4][4];
#pragma unroll
    for (int a = 0; a < 4; ++a)
#pragma unroll
        for (int b = 0; b < 4; ++b)
#pragma unroll
            for (int c = 0; c < 4; ++c) { acc[a][b][c] = 0.f; acc2[a][b][c] = 0.f; }

    auto issue = [&](int kc, int stg) {
#pragma unroll
        for (int arr = 0; arr < 4; ++arr) {
            const __half* g = (arr < 2) ? Abase[arr] : Bbase[arr - 2];
            const uint32_t sdst = sb + stg * STAGE_BYTES + arr * ARR_BYTES;
#pragma unroll
            for (int it = 0; it < 4; ++it) {
                const int id = tid + it * 256;
                const int r = id >> 3, c = id & 7;
                const void* src = g + (size_t)r * DD + kc * KC + c * 8;
                const uint32_t dst = sdst + r * 128 + ((c ^ (r & 7)) << 4);
                cpasync16(dst, src);
            }
        }
        CP_COMMIT();
    };

    issue(0, 0);
    issue(1, 1);

    for (int kc = 0; kc < NCH; ++kc) {
        if (kc + 1 < NCH) CP_WAIT1(); else CP_WAIT0();
        __syncthreads();
        if (kc + 2 < NCH) issue(kc + 2, (kc + 2) % NSTAGE);

        const uint32_t st = sb + (kc % NSTAGE) * STAGE_BYTES;
#pragma unroll
        for (int kk = 0; kk < 4; ++kk) {
            const int c16 = kk * 2 + (lane >> 4);
            uint32_t aoff[4], boff[2];
#pragma unroll
            for (int mi = 0; mi < 4; ++mi) {
                const int row = wm * 64 + mi * 16 + (lane & 15);
                aoff[mi] = row * 128 + ((c16 ^ (row & 7)) << 4);
            }
#pragma unroll
            for (int nb = 0; nb < 2; ++nb) {
                const int row = wn * 32 + nb * 16 + (lane & 15);
                boff[nb] = row * 128 + ((c16 ^ (row & 7)) << 4);
            }
            uint32_t ah[4][4], bh[2][4], au[4][4], bu[2][4];
#pragma unroll
            for (int mi = 0; mi < 4; ++mi) ldm4(ah[mi], st + OFF_AH + aoff[mi]);
#pragma unroll
            for (int nb = 0; nb < 2; ++nb) ldm4(bh[nb], st + OFF_BH + boff[nb]);
#pragma unroll
            for (int mi = 0; mi < 4; ++mi) ldm4(au[mi], st + OFF_AU + aoff[mi]);
#pragma unroll
            for (int nb = 0; nb < 2; ++nb) ldm4(bu[nb], st + OFF_BU + boff[nb]);
#pragma unroll
            for (int mi = 0; mi < 4; ++mi)
#pragma unroll
                for (int ni = 0; ni < 4; ++ni) {
                    const int nb = ni >> 1, sidx = ni & 1;
                    mma_f32(acc[mi][ni], ah[mi], bh[nb][sidx], bh[nb][sidx + 2]);
                }
#pragma unroll
            for (int mi = 0; mi < 4; ++mi)
#pragma unroll
                for (int ni = 0; ni < 4; ++ni) {
                    const int nb = ni >> 1, sidx = ni & 1;
                    mma_f32(acc2[mi][ni], au[mi], bu[nb][sidx], bu[nb][sidx + 2]);
                }
        }
    }

#pragma unroll
    for (int mi = 0; mi < 4; ++mi) {
        const int row = brow + wm * 64 + mi * 16 + (lane >> 2);
#pragma unroll
        for (int ni = 0; ni < 4; ++ni) {
            const int col = bcol + wn * 32 + ni * 8 + (lane & 3) * 2;
            float2 v0 = make_float2(fmaf(C_MAIN, acc[mi][ni][0], acc2[mi][ni][0]),
                                    fmaf(C_MAIN, acc[mi][ni][1], acc2[mi][ni][1]));
            float2 v1 = make_float2(fmaf(C_MAIN, acc[mi][ni][2], acc2[mi][ni][2]),
                                    fmaf(C_MAIN, acc[mi][ni][3], acc2[mi][ni][3]));
            if (bias) {
                const float b0 = bias[col], b1 = bias[col + 1];
                v0.x += b0; v0.y += b1; v1.x += b0; v1.y += b1;
            }
            *(float2*)&C[(size_t)row * DD + col]       = v0;
            *(float2*)&C[(size_t)(row + 8) * DD + col] = v1;
        }
    }
}

__global__ void __launch_bounds__(256, 1) qkv_bf()
{
    const int z = blockIdx.z;
    float* Cc = (z == 0) ? g_Q : ((z == 1) ? g_K : g_V);
    gemm_body(g_Ah, g_Au,
              g_Wh + (size_t)z * DD * DD, g_Wu + (size_t)z * DD * DD,
              Cc, nullptr);
}

__global__ void __launch_bounds__(256, 1) out_bf(const float* __restrict__ bo,
                                                 float* __restrict__ out)
{
    gemm_body(g_Ch, g_Cu,
              g_Wh + (size_t)3 * DD * DD, g_Wu + (size_t)3 * DD * DD,
              out, bo);
}

// ---------------------------------------------------------------------------
// Attention v2: register-tiled (unchanged from round 10)
// ---------------------------------------------------------------------------
__global__ void __launch_bounds__(256) attn_v2(float* __restrict__ attn_out)
{
    extern __shared__ float s[];
    float* Qs = s;
    float* Ks = s + 64 * QSTRIDE;
    float* Vs = Ks + 128 * KSTRIDE;
    float* Ss = Ks;

    const int tid  = threadIdx.x;
    const int warp = tid >> 5;
    const int lane = tid & 31;
    const int q0   = blockIdx.x * 64;
    const int bh   = blockIdx.y;
    const int h    = bh & (HH - 1);
    const int b    = bh >> 4;
    const int jbase = q0 - 32;

    const float* Qg = g_Q + ((size_t)(b * SS + q0)) * DD + h * 64;
    const float* Kg = g_K + (size_t)b * SS * DD + h * 64;
    const float* Vg = g_V + (size_t)b * SS * DD + h * 64;

    for (int idx = tid; idx < 64 * 16; idx += 256) {
        const int r = idx >> 4, c = idx & 15;
        *(float4*)&Qs[r * QSTRIDE + c * 4] = *(const float4*)&Qg[(size_t)r * DD + c * 4];
    }
    for (int idx = tid; idx < 128 * 16; idx += 256) {
        const int r = idx >> 4, c = idx & 15;
        const int j = jbase + r;
        if (j >= 0 && j < SS) {
            *(float4*)&Ks[r * KSTRIDE + c * 4] = *(const float4*)&Kg[(size_t)j * DD + c * 4];
            *(float4*)&Vs[r * KSTRIDE + c * 4] = *(const float4*)&Vg[(size_t)j * DD + c * 4];
        } else {
            *(float4*)&Vs[r * KSTRIDE + c * 4] = make_float4(0.f, 0.f, 0.f, 0.f);
        }
    }
    __syncthreads();

    // ---- scores ----
    const int tq = lane >> 2;
    const int tk = lane & 3;
    float sacc[8][4];
#pragma unroll
    for (int i = 0; i < 8; ++i)
#pragma unroll
        for (int j = 0; j < 4; ++j) sacc[i][j] = 0.f;

    {
        const float* Qp = Qs + tq * QSTRIDE;
        const float* Kp = Ks + (16 * warp + tk) * KSTRIDE;
#pragma unroll 4
        for (int d = 0; d < 64; ++d) {
            float qv[8], kv[4];
#pragma unroll
            for (int i = 0; i < 8; ++i) qv[i] = Qp[i * 8 * QSTRIDE + d];
#pragma unroll
            for (int j = 0; j < 4; ++j) kv[j] = Kp[j * 4 * KSTRIDE + d];
#pragma unroll
            for (int i = 0; i < 8; ++i)
#pragma unroll
                for (int j = 0; j < 4; ++j)
                    sacc[i][j] = fmaf(qv[i], kv[j], sacc[i][j]);
        }
    }
    __syncthreads();

#pragma unroll
    for (int i = 0; i < 8; ++i) {
        const int qrow = tq + 8 * i;
#pragma unroll
        for (int j = 0; j < 4; ++j) {
            const int kcol = 16 * warp + tk + 4 * j;
            const int jg = jbase + kcol;
            const bool val = (jg >= 0) && (jg < SS) &&
                             (kcol >= qrow) && (kcol <= qrow + 64);
            Ss[qrow * SST + kcol] = val ? sacc[i][j] * 0.125f : -1e30f;
        }
    }
    __syncthreads();

    // ---- softmax ----
    {
        const int r = tid >> 2, p = tid & 3;
        const int ig = q0 + r;
        const int jlo = max(0, ig - 32), jhi = min(SS - 1, ig + 32);
        const int rb = jlo - jbase, n = jhi - jlo + 1;
        float* Sr = Ss + r * SST;

        float m = -1e30f;
#pragma unroll
        for (int c4 = 0; c4 < 32; ++c4) m = fmaxf(m, Sr[p + 4 * c4]);
        m = fmaxf(m, __shfl_xor_sync(0xffffffffu, m, 1));
        m = fmaxf(m, __shfl_xor_sync(0xffffffffu, m, 2));

        float sum = 0.f;
#pragma unroll
        for (int c4 = 0; c4 < 32; ++c4) {
            const int c = p + 4 * c4;
            float e = 0.f;
            if (c >= rb && c < rb + n) e = __expf(Sr[c] - m);
            Sr[c] = e;
            sum += e;
        }
        sum += __shfl_xor_sync(0xffffffffu, sum, 1);
        sum += __shfl_xor_sync(0xffffffffu, sum, 2);
        const float inv = 1.f / sum;

        float* rowp = attn_out ? (attn_out + ((size_t)bh * SS + ig) * SS) : nullptr;
#pragma unroll
        for (int c4 = 0; c4 < 32; ++c4) {
            const int c = p + 4 * c4;
            const float pv = Sr[c] * inv;
            Sr[c] = pv;
            if (rowp && c >= rb && c < rb + n) rowp[jbase + c] = pv;
        }
    }
    __syncthreads();

    // ---- P @ V ----
    {
        const int q  = 8 * warp + (lane >> 2);
        const int dg = lane & 3;
        const float* Pr = Ss + q * SST;
        float cacc[16];
#pragma unroll
        for (int i = 0; i < 16; ++i) cacc[i] = 0.f;

        for (int k = 0; k < 128; ++k) {
            const float pk = Pr[k];
            const float* Vr = Vs + k * KSTRIDE + 4 * dg;
#pragma unroll
            for (int c = 0; c < 4; ++c) {
                const float4 v = *(const float4*)&Vr[16 * c];
                cacc[c * 4 + 0] = fmaf(pk, v.x, cacc[c * 4 + 0]);
                cacc[c * 4 + 1] = fmaf(pk, v.y, cacc[c * 4 + 1]);
                cacc[c * 4 + 2] = fmaf(pk, v.z, cacc[c * 4 + 2]);
                cacc[c * 4 + 3] = fmaf(pk, v.w, cacc[c * 4 + 3]);
            }
        }

        const size_t co = ((size_t)(b * SS + q0 + q)) * DD + h * 64;
#pragma unroll
        for (int c = 0; c < 4; ++c) {
            __half hh[4], uu[4];
#pragma unroll
            for (int e = 0; e < 4; ++e) ksplit(cacc[c * 4 + e], hh[e], uu[e]);
            const int d = 4 * dg + 16 * c;
            *(ushort4*)(g_Ch + co + d) =
                make_ushort4(*(unsigned short*)&hh[0], *(unsigned short*)&hh[1],
                             *(unsigned short*)&hh[2], *(unsigned short*)&hh[3]);
            *(ushort4*)(g_Cu + co + d) =
                make_ushort4(*(unsigned short*)&uu[0], *(unsigned short*)&uu[1],
                             *(unsigned short*)&uu[2], *(unsigned short*)&uu[3]);
        }
    }
}

// ---------------------------------------------------------------------------
extern "C" void kernel_launch(void* const* d_in, const int* in_sizes, int n_in,
                              void* d_out, int out_size)
{
    const float* q  = (const float*)d_in[0];
    const float* wq = (const float*)d_in[1];
    const float* wk = (const float*)d_in[2];
    const float* wv = (const float*)d_in[3];
    const float* wo = (const float*)d_in[4];
    const float* bo = (const float*)d_in[5];
    float* out = (float*)d_out;

    const size_t out_elems  = (size_t)BB * SS * DD;
    const bool   write_attn = (size_t)out_size > out_elems;
    float* attn = out + out_elems;

    static cudaStream_t s2 = nullptr;
    static cudaEvent_t evF = nullptr, evJ = nullptr;
    if (!s2) {
        cudaStreamCreateWithFlags(&s2, cudaStreamNonBlocking);
        cudaEventCreateWithFlags(&evF, cudaEventDisableTiming);
        cudaEventCreateWithFlags(&evJ, cudaEventDisableTiming);
        cudaFuncSetAttribute(qkv_bf,  cudaFuncAttributeMaxDynamicSharedMemorySize, GEMM_SMEM);
        cudaFuncSetAttribute(out_bf,  cudaFuncAttributeMaxDynamicSharedMemorySize, GEMM_SMEM);
        cudaFuncSetAttribute(attn_v2, cudaFuncAttributeMaxDynamicSharedMemorySize, ATT2_SMEM);
    }

    if (write_attn) {
        // Fork: custom zero-fill on side stream (co-schedules with split+qkv,
        // uses the GEMMs' idle DRAM-write bandwidth). Joined before attn.
        cudaEventRecord(evF, 0);
        cudaStreamWaitEvent(s2, evF, 0);
        const size_t n4 = (size_t)BB * HH * SS * SS / 4;   // float4 count
        zero_kernel<<<1184, 256, 0, s2>>>((float4*)attn, n4);
        cudaEventRecord(evJ, s2);
    }

    // 1) split q + weights into fp16 H / U
    split_kernel<<<8192, 256>>>(q, wq, wk, wv, wo);

    // 2) QKV projections (Karatsuba 2-MMA)
    dim3 gq3(DD / TN, MM / TM, 3);
    qkv_bf<<<gq3, 256, GEMM_SMEM>>>();

    if (write_attn) cudaStreamWaitEvent(0, evJ, 0);

    // 3) register-tiled local attention, writes split context + band
    dim3 ga(SS / 64, BB * HH);
    attn_v2<<<ga, 256, ATT2_SMEM>>>(write_attn ? attn : nullptr);

    // 4) output projection + bias (Karatsuba 2-MMA)
    dim3 go(DD / TN, MM / TM, 1);
    out_bf<<<go, 256, GEMM_SMEM>>>(bo, out);
}

// round 12
// speedup vs baseline: 1.0184x; 1.0184x over previous
#include <cuda_runtime.h>
#include <cuda_bf16.h>
#include <cuda_fp16.h>
#include <cstdint>

#define BB 2
#define SS 2048
#define DD 1024
#define HH 16
#define MM (BB*SS)             // 4096

// GEMM tiling: 128x128 tile, K-chunk 64 (128B rows, SW128 swizzle)
#define TM 128
#define TN 128
#define KC 64
#define NCH (DD/KC)            // 16
#define NSTAGE 3               // MUST be >=3: issue(kc+2) while reading kc
#define ARR_BYTES 16384        // 128 rows x 128B
#define STAGE_BYTES 65536
#define OFF_AH 0
#define OFF_AU 16384
#define OFF_BH 32768
#define OFF_BU 49152
#define GEMM_SMEM (NSTAGE*STAGE_BYTES)   // 196608

// Karatsuba combine: C = (1 - 2^-6) * acc_hh + acc_uu
#define C_MAIN 0.984375f

// Attention v2 tiling
#define QSTRIDE 68             // floats; 68 mod 32 = 4 -> 8 rows tile 32 banks
#define KSTRIDE 68
#define SST 132                // floats; 132 mod 32 = 4
#define ATT2_SMEM ((64*QSTRIDE + 128*KSTRIDE + 128*KSTRIDE)*4)   // 87040 B

// ---------------------------------------------------------------------------
// Scratch (device globals: allocation-free rule)
// ---------------------------------------------------------------------------
__device__ float g_Q[(size_t)MM * DD];
__device__ float g_K[(size_t)MM * DD];
__device__ float g_V[(size_t)MM * DD];
__device__ __half g_Ah[(size_t)MM * DD];
__device__ __half g_Au[(size_t)MM * DD];
__device__ __half g_Wh[(size_t)4 * DD * DD];   // wq,wk,wv,wo
__device__ __half g_Wu[(size_t)4 * DD * DD];
__device__ __half g_Ch[(size_t)MM * DD];
__device__ __half g_Cu[(size_t)MM * DD];

// ---------------------------------------------------------------------------
// Helpers
// ---------------------------------------------------------------------------
__device__ __forceinline__ uint32_t smem_u32(const void* p) {
    uint32_t a;
    asm("{ .reg .u64 t; cvta.to.shared.u64 t, %1; cvt.u32.u64 %0, t; }"
        : "=r"(a) : "l"(p));
    return a;
}

__device__ __forceinline__ void cpasync16(uint32_t dst, const void* src) {
    asm volatile("cp.async.cg.shared.global [%0], [%1], 16;"
                 :: "r"(dst), "l"(src));
}
#define CP_COMMIT() asm volatile("cp.async.commit_group;" ::: "memory")
#define CP_WAIT1()  asm volatile("cp.async.wait_group 1;" ::: "memory")
#define CP_WAIT0()  asm volatile("cp.async.wait_group 0;" ::: "memory")

__device__ __forceinline__ void ldm4(uint32_t* r, uint32_t addr) {
    asm volatile("ldmatrix.sync.aligned.m8n8.x4.shared.b16 {%0,%1,%2,%3}, [%4];"
                 : "=r"(r[0]), "=r"(r[1]), "=r"(r[2]), "=r"(r[3]) : "r"(addr));
}

__device__ __forceinline__ void mma_f32(float* c, const uint32_t* a,
                                        uint32_t b0, uint32_t b1) {
    asm volatile(
        "mma.sync.aligned.m16n8k16.row.col.f32.f16.f16.f32 "
        "{%0,%1,%2,%3}, {%4,%5,%6,%7}, {%8,%9}, {%0,%1,%2,%3};"
        : "+f"(c[0]), "+f"(c[1]), "+f"(c[2]), "+f"(c[3])
        : "r"(a[0]), "r"(a[1]), "r"(a[2]), "r"(a[3]), "r"(b0), "r"(b1));
}

// x -> H = fp16(x), U = fp16(2^-3*H + 2^3*(x-H))
__device__ __forceinline__ void ksplit(float x, __half& h, __half& u) {
    h = __float2half_rn(x);
    const float hf = __half2float(h);
    u = __float2half_rn(fmaf(0.125f, hf, 8.0f * (x - hf)));
}

// ---------------------------------------------------------------------------
// Split pass: q + 4 weights -> fp16 H / U
// ---------------------------------------------------------------------------
__global__ void __launch_bounds__(256) split_kernel(const float* __restrict__ q,
                                                    const float* __restrict__ wq,
                                                    const float* __restrict__ wk,
                                                    const float* __restrict__ wv,
                                                    const float* __restrict__ wo)
{
    const size_t i4 = (size_t)blockIdx.x * 256 + threadIdx.x;
    const float* src;
    __half *dh, *du;
    size_t e;
    if (i4 < 1048576) {
        src = q; e = i4;
        dh = g_Ah; du = g_Au;
    } else {
        const size_t r = i4 - 1048576;
        const int w = (int)(r >> 18);
        e = r & 262143;
        src = (w == 0) ? wq : (w == 1) ? wk : (w == 2) ? wv : wo;
        dh = g_Wh + (size_t)w * DD * DD;
        du = g_Wu + (size_t)w * DD * DD;
    }
    const float4 v = ((const float4*)src)[e];
    __half h[4], u[4];
    ksplit(v.x, h[0], u[0]); ksplit(v.y, h[1], u[1]);
    ksplit(v.z, h[2], u[2]); ksplit(v.w, h[3], u[3]);
    *(ushort4*)(dh + e * 4) = make_ushort4(*(unsigned short*)&h[0], *(unsigned short*)&h[1],
                                           *(unsigned short*)&h[2], *(unsigned short*)&h[3]);
    *(ushort4*)(du + e * 4) = make_ushort4(*(unsigned short*)&u[0], *(unsigned short*)&u[1],
                                           *(unsigned short*)&u[2], *(unsigned short*)&u[3]);
}

// ---------------------------------------------------------------------------
// fp16 Karatsuba GEMM (unchanged from round 9/10)
// ---------------------------------------------------------------------------
__device__ __forceinline__ void gemm_body(const __half* __restrict__ Ah,
                                          const __half* __restrict__ Au,
                                          const __half* __restrict__ Wh,
                                          const __half* __restrict__ Wu,
                                          float* __restrict__ C,
                                          const float* __restrict__ bias)
{
    extern __shared__ char dsm[];
    const uint32_t sb = smem_u32(dsm);
    const int tid  = threadIdx.x;
    const int wid  = tid >> 5;
    const int lane = tid & 31;
    const int wm   = wid >> 2;
    const int wn   = wid & 3;
    const int brow = blockIdx.y * TM;
    const int bcol = blockIdx.x * TN;

    const __half* Abase[2] = { Ah + (size_t)brow * DD, Au + (size_t)brow * DD };
    const __half* Bbase[2] = { Wh + (size_t)bcol * DD, Wu + (size_t)bcol * DD };

    float acc[4][4][4];
    float acc2[4][4][4];
#pragma unroll
    for (int a = 0; a < 4; ++a)
#pragma unroll
        for (int b = 0; b < 4; ++b)
#pragma unroll
            for (int c = 0; c < 4; ++c) { acc[a][b][c] = 0.f; acc2[a][b][c] = 0.f; }

    auto issue = [&](int kc, int stg) {
#pragma unroll
        for (int arr = 0; arr < 4; ++arr) {
            const __half* g = (arr < 2) ? Abase[arr] : Bbase[arr - 2];
            const uint32_t sdst = sb + stg * STAGE_BYTES + arr * ARR_BYTES;
#pragma unroll
            for (int it = 0; it < 4; ++it) {
                const int id = tid + it * 256;
                const int r = id >> 3, c = id & 7;
                const void* src = g + (size_t)r * DD + kc * KC + c * 8;
                const uint32_t dst = sdst + r * 128 + ((c ^ (r & 7)) << 4);
                cpasync16(dst, src);
            }
        }
        CP_COMMIT();
    };

    issue(0, 0);
    issue(1, 1);

    for (int kc = 0; kc < NCH; ++kc) {
        if (kc + 1 < NCH) CP_WAIT1(); else CP_WAIT0();
        __syncthreads();
        if (kc + 2 < NCH) issue(kc + 2, (kc + 2) % NSTAGE);

        const uint32_t st = sb + (kc % NSTAGE) * STAGE_BYTES;
#pragma unroll
        for (int kk = 0; kk < 4; ++kk) {
            const int c16 = kk * 2 + (lane >> 4);
            uint32_t aoff[4], boff[2];
#pragma unroll
            for (int mi = 0; mi < 4; ++mi) {
                const int row = wm * 64 + mi * 16 + (lane & 15);
                aoff[mi] = row * 128 + ((c16 ^ (row & 7)) << 4);
            }
#pragma unroll
            for (int nb = 0; nb < 2; ++nb) {
                const int row = wn * 32 + nb * 16 + (lane & 15);
                boff[nb] = row * 128 + ((c16 ^ (row & 7)) << 4);
            }
            uint32_t ah[4][4], bh[2][4], au[4][4], bu[2][4];
#pragma unroll
            for (int mi = 0; mi < 4; ++mi) ldm4(ah[mi], st + OFF_AH + aoff[mi]);
#pragma unroll
            for (int nb = 0; nb < 2; ++nb) ldm4(bh[nb], st + OFF_BH + boff[nb]);
#pragma unroll
            for (int mi = 0; mi < 4; ++mi) ldm4(au[mi], st + OFF_AU + aoff[mi]);
#pragma unroll
            for (int nb = 0; nb < 2; ++nb) ldm4(bu[nb], st + OFF_BU + boff[nb]);
#pragma unroll
            for (int mi = 0; mi < 4; ++mi)
#pragma unroll
                for (int ni = 0; ni < 4; ++ni) {
                    const int nb = ni >> 1, sidx = ni & 1;
                    mma_f32(acc[mi][ni], ah[mi], bh[nb][sidx], bh[nb][sidx + 2]);
                }
#pragma unroll
            for (int mi = 0; mi < 4; ++mi)
#pragma unroll
                for (int ni = 0; ni < 4; ++ni) {
                    const int nb = ni >> 1, sidx = ni & 1;
                    mma_f32(acc2[mi][ni], au[mi], bu[nb][sidx], bu[nb][sidx + 2]);
                }
        }
    }

#pragma unroll
    for (int mi = 0; mi < 4; ++mi) {
        const int row = brow + wm * 64 + mi * 16 + (lane >> 2);
#pragma unroll
        for (int ni = 0; ni < 4; ++ni) {
            const int col = bcol + wn * 32 + ni * 8 + (lane & 3) * 2;
            float2 v0 = make_float2(fmaf(C_MAIN, acc[mi][ni][0], acc2[mi][ni][0]),
                                    fmaf(C_MAIN, acc[mi][ni][1], acc2[mi][ni][1]));
            float2 v1 = make_float2(fmaf(C_MAIN, acc[mi][ni][2], acc2[mi][ni][2]),
                                    fmaf(C_MAIN, acc[mi][ni][3], acc2[mi][ni][3]));
            if (bias) {
                const float b0 = bias[col], b1 = bias[col + 1];
                v0.x += b0; v0.y += b1; v1.x += b0; v1.y += b1;
            }
            *(float2*)&C[(size_t)row * DD + col]       = v0;
            *(float2*)&C[(size_t)(row + 8) * DD + col] = v1;
        }
    }
}

__global__ void __launch_bounds__(256, 1) qkv_bf()
{
    const int z = blockIdx.z;
    float* Cc = (z == 0) ? g_Q : ((z == 1) ? g_K : g_V);
    gemm_body(g_Ah, g_Au,
              g_Wh + (size_t)z * DD * DD, g_Wu + (size_t)z * DD * DD,
              Cc, nullptr);
}

__global__ void __launch_bounds__(256, 1) out_bf(const float* __restrict__ bo,
                                                 float* __restrict__ out)
{
    gemm_body(g_Ch, g_Cu,
              g_Wh + (size_t)3 * DD * DD, g_Wu + (size_t)3 * DD * DD,
              out, bo);
}

// ---------------------------------------------------------------------------
// Attention v3: register-tiled with fully vectorized SMEM traffic.
//   Phase 1 (scores): warp w owns key cols [16w,16w+16); thread tile 8q x 4k;
//                     d loop in float4 steps: 12 LDS.128 per 4 d-values.
//   Phase 2 (softmax): 4 threads/row over the S tile in SMEM (aliases K).
//   Phase 3 (PV): warp w owns q rows [8w,8w+8); thread 1q x 16d; P via float4.
// ---------------------------------------------------------------------------
__global__ void __launch_bounds__(256) attn_v3(float* __restrict__ attn_out)
{
    extern __shared__ float s[];
    float* Qs = s;
    float* Ks = s + 64 * QSTRIDE;
    float* Vs = Ks + 128 * KSTRIDE;
    float* Ss = Ks;                        // aliases Ks after scores

    const int tid  = threadIdx.x;
    const int warp = tid >> 5;
    const int lane = tid & 31;
    const int q0   = blockIdx.x * 64;
    const int bh   = blockIdx.y;
    const int h    = bh & (HH - 1);
    const int b    = bh >> 4;
    const int jbase = q0 - 32;

    const float* Qg = g_Q + ((size_t)(b * SS + q0)) * DD + h * 64;
    const float* Kg = g_K + (size_t)b * SS * DD + h * 64;
    const float* Vg = g_V + (size_t)b * SS * DD + h * 64;

    for (int idx = tid; idx < 64 * 16; idx += 256) {
        const int r = idx >> 4, c = idx & 15;
        *(float4*)&Qs[r * QSTRIDE + c * 4] = *(const float4*)&Qg[(size_t)r * DD + c * 4];
    }
    for (int idx = tid; idx < 128 * 16; idx += 256) {
        const int r = idx >> 4, c = idx & 15;
        const int j = jbase + r;
        if (j >= 0 && j < SS) {
            *(float4*)&Ks[r * KSTRIDE + c * 4] = *(const float4*)&Kg[(size_t)j * DD + c * 4];
            *(float4*)&Vs[r * KSTRIDE + c * 4] = *(const float4*)&Vg[(size_t)j * DD + c * 4];
        } else {
            *(float4*)&Vs[r * KSTRIDE + c * 4] = make_float4(0.f, 0.f, 0.f, 0.f);
        }
    }
    __syncthreads();

    // ---- scores (float4 d-steps) ----
    const int tq = lane >> 2;      // 0..7
    const int tk = lane & 3;       // 0..3
    float sacc[8][4];
#pragma unroll
    for (int i = 0; i < 8; ++i)
#pragma unroll
        for (int j = 0; j < 4; ++j) sacc[i][j] = 0.f;

    {
        const float4* Qp = (const float4*)(Qs + tq * QSTRIDE);            // +i*8 rows = +i*136 f4
        const float4* Kp = (const float4*)(Ks + (16 * warp + tk) * KSTRIDE); // +j*4 rows = +j*68 f4
#pragma unroll
        for (int d4 = 0; d4 < 16; ++d4) {
            float4 qv[8], kv[4];
#pragma unroll
            for (int i = 0; i < 8; ++i) qv[i] = Qp[i * 136 + d4];
#pragma unroll
            for (int j = 0; j < 4; ++j) kv[j] = Kp[j * 68 + d4];
#pragma unroll
            for (int i = 0; i < 8; ++i)
#pragma unroll
                for (int j = 0; j < 4; ++j) {
                    sacc[i][j] = fmaf(qv[i].x, kv[j].x, sacc[i][j]);
                    sacc[i][j] = fmaf(qv[i].y, kv[j].y, sacc[i][j]);
                    sacc[i][j] = fmaf(qv[i].z, kv[j].z, sacc[i][j]);
                    sacc[i][j] = fmaf(qv[i].w, kv[j].w, sacc[i][j]);
                }
        }
    }
    __syncthreads();   // all Ks reads done before Ss (alias) is written

#pragma unroll
    for (int i = 0; i < 8; ++i) {
        const int qrow = tq + 8 * i;
#pragma unroll
        for (int j = 0; j < 4; ++j) {
            const int kcol = 16 * warp + tk + 4 * j;
            const int jg = jbase + kcol;
            const bool val = (jg >= 0) && (jg < SS) &&
                             (kcol >= qrow) && (kcol <= qrow + 64);
            Ss[qrow * SST + kcol] = val ? sacc[i][j] * 0.125f : -1e30f;
        }
    }
    __syncthreads();

    // ---- softmax (4 threads per row) ----
    {
        const int r = tid >> 2, p = tid & 3;
        const int ig = q0 + r;
        const int jlo = max(0, ig - 32), jhi = min(SS - 1, ig + 32);
        const int rb = jlo - jbase, n = jhi - jlo + 1;
        float* Sr = Ss + r * SST;

        float m = -1e30f;
#pragma unroll
        for (int c4 = 0; c4 < 32; ++c4) m = fmaxf(m, Sr[p + 4 * c4]);
        m = fmaxf(m, __shfl_xor_sync(0xffffffffu, m, 1));
        m = fmaxf(m, __shfl_xor_sync(0xffffffffu, m, 2));

        float sum = 0.f;
#pragma unroll
        for (int c4 = 0; c4 < 32; ++c4) {
            const int c = p + 4 * c4;
            float e = 0.f;
            if (c >= rb && c < rb + n) e = __expf(Sr[c] - m);
            Sr[c] = e;
            sum += e;
        }
        sum += __shfl_xor_sync(0xffffffffu, sum, 1);
        sum += __shfl_xor_sync(0xffffffffu, sum, 2);
        const float inv = 1.f / sum;

        float* rowp = attn_out ? (attn_out + ((size_t)bh * SS + ig) * SS) : nullptr;
#pragma unroll
        for (int c4 = 0; c4 < 32; ++c4) {
            const int c = p + 4 * c4;
            const float pv = Sr[c] * inv;
            Sr[c] = pv;
            if (rowp && c >= rb && c < rb + n) rowp[jbase + c] = pv;
        }
    }
    __syncthreads();

    // ---- P @ V (float4 P loads) ----
    {
        const int q  = 8 * warp + (lane >> 2);
        const int dg = lane & 3;
        const float4* Pr4 = (const float4*)(Ss + q * SST);   // SST=132 -> 33 f4/row
        float cacc[16];
#pragma unroll
        for (int i = 0; i < 16; ++i) cacc[i] = 0.f;

        const float* Vbase = Vs + 4 * dg;
#pragma unroll 4
        for (int k4 = 0; k4 < 32; ++k4) {
            const float4 p4 = Pr4[k4];
            const float pk[4] = { p4.x, p4.y, p4.z, p4.w };
#pragma unroll
            for (int kk = 0; kk < 4; ++kk) {
                const float* Vr = Vbase + (k4 * 4 + kk) * KSTRIDE;
#pragma unroll
                for (int c = 0; c < 4; ++c) {
                    const float4 v = *(const float4*)&Vr[16 * c];
                    cacc[c * 4 + 0] = fmaf(pk[kk], v.x, cacc[c * 4 + 0]);
                    cacc[c * 4 + 1] = fmaf(pk[kk], v.y, cacc[c * 4 + 1]);
                    cacc[c * 4 + 2] = fmaf(pk[kk], v.z, cacc[c * 4 + 2]);
                    cacc[c * 4 + 3] = fmaf(pk[kk], v.w, cacc[c * 4 + 3]);
                }
            }
        }

        const size_t co = ((size_t)(b * SS + q0 + q)) * DD + h * 64;
#pragma unroll
        for (int c = 0; c < 4; ++c) {
            __half hh[4], uu[4];
#pragma unroll
            for (int e = 0; e < 4; ++e) ksplit(cacc[c * 4 + e], hh[e], uu[e]);
            const int d = 4 * dg + 16 * c;
            *(ushort4*)(g_Ch + co + d) =
                make_ushort4(*(unsigned short*)&hh[0], *(unsigned short*)&hh[1],
                             *(unsigned short*)&hh[2], *(unsigned short*)&hh[3]);
            *(ushort4*)(g_Cu + co + d) =
                make_ushort4(*(unsigned short*)&uu[0], *(unsigned short*)&uu[1],
                             *(unsigned short*)&uu[2], *(unsigned short*)&uu[3]);
        }
    }
}

// ---------------------------------------------------------------------------
extern "C" void kernel_launch(void* const* d_in, const int* in_sizes, int n_in,
                              void* d_out, int out_size)
{
    const float* q  = (const float*)d_in[0];
    const float* wq = (const float*)d_in[1];
    const float* wk = (const float*)d_in[2];
    const float* wv = (const float*)d_in[3];
    const float* wo = (const float*)d_in[4];
    const float* bo = (const float*)d_in[5];
    float* out = (float*)d_out;

    const size_t out_elems  = (size_t)BB * SS * DD;
    const bool   write_attn = (size_t)out_size > out_elems;
    float* attn = out + out_elems;

    static cudaStream_t s2 = nullptr;
    static cudaEvent_t evF = nullptr, evJ = nullptr;
    if (!s2) {
        cudaStreamCreateWithFlags(&s2, cudaStreamNonBlocking);
        cudaEventCreateWithFlags(&evF, cudaEventDisableTiming);
        cudaEventCreateWithFlags(&evJ, cudaEventDisableTiming);
        cudaFuncSetAttribute(qkv_bf,  cudaFuncAttributeMaxDynamicSharedMemorySize, GEMM_SMEM);
        cudaFuncSetAttribute(out_bf,  cudaFuncAttributeMaxDynamicSharedMemorySize, GEMM_SMEM);
        cudaFuncSetAttribute(attn_v3, cudaFuncAttributeMaxDynamicSharedMemorySize, ATT2_SMEM);
    }

    if (write_attn) {
        cudaEventRecord(evF, 0);
        cudaStreamWaitEvent(s2, evF, 0);
        cudaMemsetAsync(attn, 0, (size_t)BB * HH * SS * SS * sizeof(float), s2);
        cudaEventRecord(evJ, s2);
    }

    // 1) split q + weights into fp16 H / U
    split_kernel<<<8192, 256>>>(q, wq, wk, wv, wo);

    // 2) QKV projections (Karatsuba 2-MMA)
    dim3 gq3(DD / TN, MM / TM, 3);
    qkv_bf<<<gq3, 256, GEMM_SMEM>>>();

    if (write_attn) cudaStreamWaitEvent(0, evJ, 0);

    // 3) register-tiled local attention (vectorized), split context + band
    dim3 ga(SS / 64, BB * HH);
    attn_v3<<<ga, 256, ATT2_SMEM>>>(write_attn ? attn : nullptr);

    // 4) output projection + bias (Karatsuba 2-MMA)
    dim3 go(DD / TN, MM / TM, 1);
    out_bf<<<go, 256, GEMM_SMEM>>>(bo, out);
}